// round 8
// baseline (speedup 1.0000x reference)
#include <cuda_runtime.h>
#include <math.h>

#define Bdim 256
#define Jdim 64
#define Ddim 512
#define SST 516      // s tile row stride (floats): bank = 4*gid+tig -> conflict-free
#define UST 520      // U slab row stride (uints):  bank = 8*tig+gid -> conflict-free

// Scratch (allocation-free rule: __device__ globals)
__device__ float    g_Q[Bdim * Ddim];      // inputs @ W
__device__ float    g_P[Jdim * Ddim];      // keys @ V + U_bias
__device__ unsigned g_Uhi[Ddim * Ddim];    // tf32(U)
__device__ unsigned g_Ulo[Ddim * Ddim];    // tf32(U - tf32(U))

// ---------------- cp.async helpers ----------------
__device__ __forceinline__ void cp_async16(void* smem_dst, const void* gmem_src) {
    unsigned s = (unsigned)__cvta_generic_to_shared(smem_dst);
    asm volatile("cp.async.cg.shared.global [%0], [%1], 16;\n" :: "r"(s), "l"(gmem_src));
}
__device__ __forceinline__ void cp_commit() { asm volatile("cp.async.commit_group;\n"); }
__device__ __forceinline__ void cp_wait1()  { asm volatile("cp.async.wait_group 1;\n"); }
__device__ __forceinline__ void cp_wait0()  { asm volatile("cp.async.wait_group 0;\n"); }

// ---------------- tf32 helpers ----------------
__device__ __forceinline__ unsigned f2tf32(float x) {
    unsigned r;
    asm("cvt.rna.tf32.f32 %0, %1;" : "=r"(r) : "f"(x));
    return r;
}
__device__ __forceinline__ void split_tf32(float x, unsigned& hi, unsigned& lo) {
    hi = f2tf32(x);
    float h = __uint_as_float(hi);
    lo = f2tf32(x - h);
}
// D += A(16x8,row) * B(8x8,col)   (tf32 in, fp32 acc)
__device__ __forceinline__ void mma_tf32(float d[4], const unsigned a[4], const unsigned b[2]) {
    asm volatile("mma.sync.aligned.m16n8k8.row.col.f32.tf32.tf32.f32 "
        "{%0,%1,%2,%3}, {%4,%5,%6,%7}, {%8,%9}, {%0,%1,%2,%3};"
        : "+f"(d[0]), "+f"(d[1]), "+f"(d[2]), "+f"(d[3])
        : "r"(a[0]), "r"(a[1]), "r"(a[2]), "r"(a[3]), "r"(b[0]), "r"(b[1]));
}

// ---------------- precompute: Q = inputs@W ; P = keys@V + bias ; split(U) ----------------
__device__ __forceinline__ void sgemm_tile_body(
    const float* __restrict__ A, const float* __restrict__ Bm,
    const float* __restrict__ bias, float* __restrict__ C,
    int m0, int n0, int N, int K,
    float (*As)[64], float (*Bs)[64])
{
    int tid = threadIdx.x;
    int ty = tid >> 4, tx = tid & 15;
    float acc[4][4];
#pragma unroll
    for (int i = 0; i < 4; i++)
#pragma unroll
        for (int j = 0; j < 4; j++) acc[i][j] = 0.f;

    for (int k0 = 0; k0 < K; k0 += 16) {
        {
            int m  = tid >> 2;
            int kk = (tid & 3) * 4;
            float4 v = *reinterpret_cast<const float4*>(&A[(size_t)(m0 + m) * K + k0 + kk]);
            As[kk + 0][m] = v.x; As[kk + 1][m] = v.y;
            As[kk + 2][m] = v.z; As[kk + 3][m] = v.w;
        }
        {
            int kk = tid >> 4;
            int c4 = (tid & 15) * 4;
            *reinterpret_cast<float4*>(&Bs[kk][c4]) =
                *reinterpret_cast<const float4*>(&Bm[(size_t)(k0 + kk) * N + n0 + c4]);
        }
        __syncthreads();
#pragma unroll
        for (int kk = 0; kk < 16; kk++) {
            float4 a4 = *reinterpret_cast<const float4*>(&As[kk][ty * 4]);
            float4 b4 = *reinterpret_cast<const float4*>(&Bs[kk][tx * 4]);
            float a[4] = {a4.x, a4.y, a4.z, a4.w};
            float b[4] = {b4.x, b4.y, b4.z, b4.w};
#pragma unroll
            for (int i = 0; i < 4; i++)
#pragma unroll
                for (int j = 0; j < 4; j++) acc[i][j] += a[i] * b[j];
        }
        __syncthreads();
    }
    float bx = 0.f, by = 0.f, bz = 0.f, bw = 0.f;
    if (bias) {
        bx = bias[n0 + tx * 4 + 0]; by = bias[n0 + tx * 4 + 1];
        bz = bias[n0 + tx * 4 + 2]; bw = bias[n0 + tx * 4 + 3];
    }
#pragma unroll
    for (int i = 0; i < 4; i++) {
        float4 o;
        o.x = acc[i][0] + bx; o.y = acc[i][1] + by;
        o.z = acc[i][2] + bz; o.w = acc[i][3] + bw;
        *reinterpret_cast<float4*>(&C[(size_t)(m0 + ty * 4 + i) * N + n0 + tx * 4]) = o;
    }
}

__global__ __launch_bounds__(256) void precompute_kernel(
    const float* __restrict__ inputs, const float* __restrict__ keys,
    const float* __restrict__ V, const float* __restrict__ W,
    const float* __restrict__ U, const float* __restrict__ Ubias)
{
    __shared__ float As[16][64];
    __shared__ float Bs[16][64];
    int bx = blockIdx.x;
    if (bx < 32) {
        sgemm_tile_body(inputs, W, nullptr, g_Q,
                        (bx >> 3) * 64, (bx & 7) * 64, Ddim, Ddim, As, Bs);
    } else if (bx < 40) {
        int t = bx - 32;
        sgemm_tile_body(keys, V, Ubias, g_P,
                        0, t * 64, Ddim, Ddim, As, Bs);
    } else {
        // split U into hi/lo tf32 arrays: 64 blocks x 256 threads x 16 elems
        int t = bx - 40;
        int base = t * 4096 + threadIdx.x * 16;
#pragma unroll
        for (int q = 0; q < 4; q++) {
            int i = base + q * 4;
            float4 u = *reinterpret_cast<const float4*>(&U[i]);
            uint4 hi, lo;
            split_tf32(u.x, hi.x, lo.x);
            split_tf32(u.y, hi.y, lo.y);
            split_tf32(u.z, hi.z, lo.z);
            split_tf32(u.w, hi.w, lo.w);
            *reinterpret_cast<uint4*>(&g_Uhi[i]) = hi;
            *reinterpret_cast<uint4*>(&g_Ulo[i]) = lo;
        }
    }
}

// ---------------- fused main kernel ----------------
// CTA = 32 rows (one b, 32 j's) x 512 cols, 256 threads, 8 warps across columns.
// Two k-passes: pass1 streams Uhi (ah*bh + al*bh), pass2 streams Ulo (ah*bl).
__global__ __launch_bounds__(256, 2) void fused_kernel(
    const float* __restrict__ inputs,
    const float* __restrict__ state,
    const float* __restrict__ keys,
    float* __restrict__ out)
{
    extern __shared__ char smraw[];
    float*    s_sm  = reinterpret_cast<float*>(smraw);                       // [32][SST]
    unsigned* Ubuf  = reinterpret_cast<unsigned*>(smraw + 32 * SST * 4);     // 2 x [8][UST]
    float*    inp   = reinterpret_cast<float*>(smraw + 32 * SST * 4 + 2 * 8 * UST * 4);
    float*    qb    = inp + Ddim;
    float*    gate  = qb + Ddim;        // [32]
    float*    normv = gate + 32;        // [32]
    float*    red   = normv + 32;       // [8][32]

    int tid  = threadIdx.x;
    int bx   = blockIdx.x;
    int row0 = bx * 32;
    int b    = bx >> 1;
    int j0   = (bx & 1) * 32;
    const float* srow = state + (size_t)row0 * Ddim;

    int lane = tid & 31;
    int w    = tid >> 5;              // 0..7, column warp
    int gid  = lane >> 2;             // 0..7
    int tig  = lane & 3;              // 0..3
    int cb   = w * 64;                // warp column base

    // Prefetch Uhi slabs 0 and 1 (each 8 x 512 uints = 16KB)
#pragma unroll
    for (int q = 0; q < 4; q++) {
        int c = tid + 256 * q;
        int kk = c >> 7, off = (c & 127) * 4;
        cp_async16(Ubuf + kk * UST + off, g_Uhi + (size_t)kk * Ddim + off);
    }
    cp_commit();
#pragma unroll
    for (int q = 0; q < 4; q++) {
        int c = tid + 256 * q;
        int kk = c >> 7, off = (c & 127) * 4;
        cp_async16(Ubuf + 8 * UST + kk * UST + off, g_Uhi + (size_t)(8 + kk) * Ddim + off);
    }
    cp_commit();

    // Stage inputs[b] and Q[b]
    if (tid < 128)
        reinterpret_cast<float4*>(inp)[tid] =
            reinterpret_cast<const float4*>(inputs + (size_t)b * Ddim)[tid];
    else
        reinterpret_cast<float4*>(qb)[tid - 128] =
            reinterpret_cast<const float4*>(g_Q + (size_t)b * Ddim)[tid - 128];

    // Stage s block [32][512] -> padded [32][SST]
#pragma unroll
    for (int q = 0; q < 16; q++) {
        int c = tid + 256 * q;
        int r = c >> 7;
        int f4 = c & 127;
        float4 v = reinterpret_cast<const float4*>(srow + (size_t)r * Ddim)[f4];
        *reinterpret_cast<float4*>(&s_sm[r * SST + f4 * 4]) = v;
    }
    __syncthreads();

    // Gates: warp w -> rows w*4..w*4+3 ; arg = inputs.(s_j + key_j)
#pragma unroll
    for (int i = 0; i < 4; i++) {
        int r = w * 4 + i;
        const float* kr = keys + (size_t)(j0 + r) * Ddim;
        const float* sr = s_sm + r * SST;
        float z = 0.f;
        for (int k = lane; k < Ddim; k += 32)
            z += inp[k] * (sr[k] + kr[k]);
#pragma unroll
        for (int o = 16; o; o >>= 1) z += __shfl_xor_sync(0xffffffffu, z, o);
        if (lane == 0) gate[r] = 1.f / (1.f + expf(-z));
    }

    // -------- tf32 split-3 MMA mainloop (128 virtual slabs: 64 hi + 64 lo) --------
    float acc[2][8][4];
#pragma unroll
    for (int mi = 0; mi < 2; mi++)
#pragma unroll
        for (int nf = 0; nf < 8; nf++)
#pragma unroll
            for (int c = 0; c < 4; c++) acc[mi][nf][c] = 0.f;

#pragma unroll 1
    for (int v = 0; v < 128; v++) {
        if (v < 126) cp_wait1(); else cp_wait0();
        __syncthreads();
        const unsigned* Ub = Ubuf + (v & 1) * (8 * UST);
        int k0 = (v & 63) * 8;
        bool hipass = (v < 64);

        // A fragments: rows mi*16 + {gid, gid+8}, cols k0 + {tig, tig+4}
        unsigned ah[2][4], al[2][4];
#pragma unroll
        for (int mi = 0; mi < 2; mi++) {
            const float* Sb = s_sm + (mi * 16 + gid) * SST + k0 + tig;
            float f0 = Sb[0];
            float f1 = Sb[8 * SST];
            float f2 = Sb[4];
            float f3 = Sb[8 * SST + 4];
            if (hipass) {
                split_tf32(f0, ah[mi][0], al[mi][0]);
                split_tf32(f1, ah[mi][1], al[mi][1]);
                split_tf32(f2, ah[mi][2], al[mi][2]);
                split_tf32(f3, ah[mi][3], al[mi][3]);
            } else {
                ah[mi][0] = f2tf32(f0);
                ah[mi][1] = f2tf32(f1);
                ah[mi][2] = f2tf32(f2);
                ah[mi][3] = f2tf32(f3);
            }
        }

#pragma unroll
        for (int nf = 0; nf < 8; nf++) {
            int col = cb + nf * 8 + gid;
            unsigned bb[2];
            bb[0] = Ub[tig * UST + col];
            bb[1] = Ub[(tig + 4) * UST + col];
#pragma unroll
            for (int mi = 0; mi < 2; mi++) {
                mma_tf32(acc[mi][nf], ah[mi], bb);
                if (hipass) mma_tf32(acc[mi][nf], al[mi], bb);
            }
        }
        __syncthreads();
        if (v + 2 < 128) {
            int nv = v + 2;
            const unsigned* Ug = (nv < 64)
                ? g_Uhi + (size_t)nv * 8 * Ddim
                : g_Ulo + (size_t)(nv - 64) * 8 * Ddim;
            unsigned* Ud = Ubuf + (v & 1) * (8 * UST);
#pragma unroll
            for (int q = 0; q < 4; q++) {
                int c = tid + 256 * q;
                int kk = c >> 7, off = (c & 127) * 4;
                cp_async16(Ud + kk * UST + off, Ug + (size_t)kk * Ddim + off);
            }
            cp_commit();
        }
    }

    // -------- epilogue: v = s + g*relu(acc + qb + P), row-norm partials --------
    float part[4];
#pragma unroll
    for (int mi = 0; mi < 2; mi++) {
#pragma unroll
        for (int h = 0; h < 2; h++) {
            int r = mi * 16 + h * 8 + gid;          // 0..31
            float g = gate[r];
            const float* Pr = g_P + (size_t)(j0 + r) * Ddim;
            const float* Sr = s_sm + r * SST;
            float psum = 0.f;
#pragma unroll
            for (int nf = 0; nf < 8; nf++) {
                int c0 = cb + nf * 8 + tig * 2;
                float2 p2 = *reinterpret_cast<const float2*>(Pr + c0);
                float2 s2 = *reinterpret_cast<const float2*>(Sr + c0);
                float pre0 = acc[mi][nf][h * 2 + 0] + qb[c0]     + p2.x;
                float pre1 = acc[mi][nf][h * 2 + 1] + qb[c0 + 1] + p2.y;
                float v0 = s2.x + g * fmaxf(pre0, 0.f);
                float v1 = s2.y + g * fmaxf(pre1, 0.f);
                acc[mi][nf][h * 2 + 0] = v0;
                acc[mi][nf][h * 2 + 1] = v1;
                psum += v0 * v0 + v1 * v1;
            }
            part[mi * 2 + h] = psum;
        }
    }
#pragma unroll
    for (int i = 0; i < 4; i++) {
        part[i] += __shfl_xor_sync(0xffffffffu, part[i], 1);
        part[i] += __shfl_xor_sync(0xffffffffu, part[i], 2);
    }
    if (tig == 0) {
#pragma unroll
        for (int mi = 0; mi < 2; mi++)
#pragma unroll
            for (int h = 0; h < 2; h++)
                red[w * 32 + mi * 16 + h * 8 + gid] = part[mi * 2 + h];
    }
    __syncthreads();
    if (tid < 32) {
        float sum = 0.f;
#pragma unroll
        for (int ww = 0; ww < 8; ww++) sum += red[ww * 32 + tid];
        normv[tid] = fmaxf(sqrtf(sum), 1e-12f);
    }
    __syncthreads();

    // out = (v > 0) ? norm : v
#pragma unroll
    for (int mi = 0; mi < 2; mi++) {
#pragma unroll
        for (int h = 0; h < 2; h++) {
            int r = mi * 16 + h * 8 + gid;
            float n = normv[r];
            float* orow = out + (size_t)(row0 + r) * Ddim;
#pragma unroll
            for (int nf = 0; nf < 8; nf++) {
                int c0 = cb + nf * 8 + tig * 2;
                float v0 = acc[mi][nf][h * 2 + 0];
                float v1 = acc[mi][nf][h * 2 + 1];
                float2 o;
                o.x = v0 > 0.f ? n : v0;
                o.y = v1 > 0.f ? n : v1;
                *reinterpret_cast<float2*>(orow + c0) = o;
            }
        }
    }
}

extern "C" void kernel_launch(void* const* d_in, const int* in_sizes, int n_in,
                              void* d_out, int out_size)
{
    const float* inputs = (const float*)d_in[0];
    const float* state  = (const float*)d_in[1];
    const float* keys   = (const float*)d_in[2];
    const float* U      = (const float*)d_in[3];
    const float* V      = (const float*)d_in[4];
    const float* W      = (const float*)d_in[5];
    const float* Ubias  = (const float*)d_in[6];
    float* out = (float*)d_out;
    (void)in_sizes; (void)n_in; (void)out_size;

    // Q = inputs@W (32 blks), P = keys@V + bias (8 blks), U hi/lo split (64 blks)
    precompute_kernel<<<104, 256>>>(inputs, keys, V, W, U, Ubias);

    size_t smem = (size_t)32 * SST * 4          // s tile        (66,048 B)
                + (size_t)2 * 8 * UST * 4       // U double buf  (33,280 B)
                + (Ddim + Ddim + 32 + 32 + 8 * 32) * 4;   // inp/qb/gate/norm/red
    cudaFuncSetAttribute(fused_kernel, cudaFuncAttributeMaxDynamicSharedMemorySize, (int)smem);
    fused_kernel<<<(Bdim * Jdim) / 32, 256, smem>>>(inputs, state, keys, out);
}

// round 9
// speedup vs baseline: 1.2185x; 1.2185x over previous
#include <cuda_runtime.h>
#include <math.h>

#define Bdim 256
#define Jdim 64
#define Ddim 512

// Scratch (allocation-free rule: __device__ globals)
__device__ float g_Q[Bdim * Ddim];     // inputs @ W
__device__ float g_P[Jdim * Ddim];     // keys @ V + U_bias
// U pre-split, transposed, k-interleaved:
// g_U2T[(col*64 + s)*4 + p] = { hi(U[8s+p][col]), lo(U[8s+p][col]),
//                               hi(U[8s+p+4][col]), lo(U[8s+p+4][col]) }
__device__ uint4 g_U2T[Ddim * 64 * 4];

// ---------------- cp.async helpers ----------------
__device__ __forceinline__ void cp_async16(void* smem_dst, const void* gmem_src) {
    unsigned s = (unsigned)__cvta_generic_to_shared(smem_dst);
    asm volatile("cp.async.cg.shared.global [%0], [%1], 16;\n" :: "r"(s), "l"(gmem_src));
}
__device__ __forceinline__ void cp_commit() { asm volatile("cp.async.commit_group;\n"); }
__device__ __forceinline__ void cp_wait1()  { asm volatile("cp.async.wait_group 1;\n"); }
__device__ __forceinline__ void cp_wait0()  { asm volatile("cp.async.wait_group 0;\n"); }

// ---------------- tf32 helpers ----------------
__device__ __forceinline__ unsigned f2tf32(float x) {
    unsigned r;
    asm("cvt.rna.tf32.f32 %0, %1;" : "=r"(r) : "f"(x));
    return r;
}
__device__ __forceinline__ void split_tf32(float x, unsigned& hi, unsigned& lo) {
    hi = f2tf32(x);
    float h = __uint_as_float(hi);
    lo = f2tf32(x - h);
}
// D += A(16x8,row) * B(8x8,col)   (tf32 in, fp32 acc)
__device__ __forceinline__ void mma_tf32(float d[4], const unsigned a[4], const unsigned b[2]) {
    asm volatile("mma.sync.aligned.m16n8k8.row.col.f32.tf32.tf32.f32 "
        "{%0,%1,%2,%3}, {%4,%5,%6,%7}, {%8,%9}, {%0,%1,%2,%3};"
        : "+f"(d[0]), "+f"(d[1]), "+f"(d[2]), "+f"(d[3])
        : "r"(a[0]), "r"(a[1]), "r"(a[2]), "r"(a[3]), "r"(b[0]), "r"(b[1]));
}

// ---------------- precompute: Q, P, and U2T ----------------
__device__ __forceinline__ void sgemm_tile_body(
    const float* __restrict__ A, const float* __restrict__ Bm,
    const float* __restrict__ bias, float* __restrict__ C,
    int m0, int n0, int N, int K,
    float (*As)[64], float (*Bs)[64])
{
    int tid = threadIdx.x;
    int ty = tid >> 4, tx = tid & 15;
    float acc[4][4];
#pragma unroll
    for (int i = 0; i < 4; i++)
#pragma unroll
        for (int j = 0; j < 4; j++) acc[i][j] = 0.f;

    for (int k0 = 0; k0 < K; k0 += 16) {
        {
            int m  = tid >> 2;
            int kk = (tid & 3) * 4;
            float4 v = *reinterpret_cast<const float4*>(&A[(size_t)(m0 + m) * K + k0 + kk]);
            As[kk + 0][m] = v.x; As[kk + 1][m] = v.y;
            As[kk + 2][m] = v.z; As[kk + 3][m] = v.w;
        }
        {
            int kk = tid >> 4;
            int c4 = (tid & 15) * 4;
            *reinterpret_cast<float4*>(&Bs[kk][c4]) =
                *reinterpret_cast<const float4*>(&Bm[(size_t)(k0 + kk) * N + n0 + c4]);
        }
        __syncthreads();
#pragma unroll
        for (int kk = 0; kk < 16; kk++) {
            float4 a4 = *reinterpret_cast<const float4*>(&As[kk][ty * 4]);
            float4 b4 = *reinterpret_cast<const float4*>(&Bs[kk][tx * 4]);
            float a[4] = {a4.x, a4.y, a4.z, a4.w};
            float b[4] = {b4.x, b4.y, b4.z, b4.w};
#pragma unroll
            for (int i = 0; i < 4; i++)
#pragma unroll
                for (int j = 0; j < 4; j++) acc[i][j] += a[i] * b[j];
        }
        __syncthreads();
    }
    float bx = 0.f, by = 0.f, bz = 0.f, bw = 0.f;
    if (bias) {
        bx = bias[n0 + tx * 4 + 0]; by = bias[n0 + tx * 4 + 1];
        bz = bias[n0 + tx * 4 + 2]; bw = bias[n0 + tx * 4 + 3];
    }
#pragma unroll
    for (int i = 0; i < 4; i++) {
        float4 o;
        o.x = acc[i][0] + bx; o.y = acc[i][1] + by;
        o.z = acc[i][2] + bz; o.w = acc[i][3] + bw;
        *reinterpret_cast<float4*>(&C[(size_t)(m0 + ty * 4 + i) * N + n0 + tx * 4]) = o;
    }
}

__global__ __launch_bounds__(256) void precompute_kernel(
    const float* __restrict__ inputs, const float* __restrict__ keys,
    const float* __restrict__ V, const float* __restrict__ W,
    const float* __restrict__ U, const float* __restrict__ Ubias)
{
    __shared__ float As[16][64];
    __shared__ float Bs[16][64];
    int bx = blockIdx.x;
    if (bx < 32) {
        sgemm_tile_body(inputs, W, nullptr, g_Q,
                        (bx >> 3) * 64, (bx & 7) * 64, Ddim, Ddim, As, Bs);
    } else if (bx < 40) {
        int t = bx - 32;
        sgemm_tile_body(keys, V, Ubias, g_P,
                        0, t * 64, Ddim, Ddim, As, Bs);
    } else {
        // U -> g_U2T : 128 blocks x 256 threads, each thread one (col, s) pair
        int id = (bx - 40) * 256 + threadIdx.x;   // 0..32767
        int col = id >> 6;
        int s   = id & 63;
#pragma unroll
        for (int p = 0; p < 4; p++) {
            float a = U[(size_t)(8 * s + p) * Ddim + col];
            float b = U[(size_t)(8 * s + p + 4) * Ddim + col];
            uint4 o;
            split_tf32(a, o.x, o.y);
            split_tf32(b, o.z, o.w);
            g_U2T[((size_t)col * 64 + s) * 4 + p] = o;
        }
    }
}

// ---------------- fused main kernel (barrier-free mainloop) ----------------
// CTA = 32 rows (one b, 32 j's) x 512 cols, 256 threads, 8 column-warps.
// Each warp owns a disjoint 64-col slice: private B double buffer, cp.async +
// __syncwarp only. A fragments read from global state (L1-cached, shared rows).
__global__ __launch_bounds__(256, 2) void fused_kernel(
    const float* __restrict__ inputs,
    const float* __restrict__ state,
    const float* __restrict__ keys,
    float* __restrict__ out)
{
    extern __shared__ char smraw[];
    uint4* Bbuf  = reinterpret_cast<uint4*>(smraw);                 // 8 warps x [2][64][4] uint4 = 64KB
    float* gate  = reinterpret_cast<float*>(smraw + 65536);         // [32]
    float* normv = gate + 32;                                        // [32]
    float* red   = normv + 32;                                       // [8][32]

    int tid  = threadIdx.x;
    int bx   = blockIdx.x;
    int row0 = bx * 32;
    int b    = bx >> 1;
    int j0   = (bx & 1) * 32;

    int lane = tid & 31;
    int w    = tid >> 5;              // 0..7 (column warp)
    int gid  = lane >> 2;             // 0..7
    int tig  = lane & 3;              // 0..3
    int cb   = w * 64;                // warp column base

    uint4* mybuf = Bbuf + w * 512;    // [2][64][4] uint4 (8KB)
    const uint4* usrc = g_U2T + (size_t)cb * 256;   // col-major: col*256 + s*4 + p

    // Per-warp prefetch of slabs 0 and 1
#pragma unroll
    for (int st = 0; st < 2; st++) {
#pragma unroll
        for (int q = 0; q < 8; q++) {
            int idx = lane + 32 * q;                 // 0..255
            int col = idx >> 2, p = idx & 3;
            cp_async16(mybuf + st * 256 + idx, usrc + (size_t)col * 256 + st * 4 + p);
        }
        cp_commit();
    }

    // Gates: warp w -> rows 4w..4w+3 ; z = inputs[b] . (s_row + key_j); all global reads
    {
        const float* ir = inputs + (size_t)b * Ddim;
#pragma unroll
        for (int i = 0; i < 4; i++) {
            int r = w * 4 + i;
            const float* sr = state + (size_t)(row0 + r) * Ddim;
            const float* kr = keys + (size_t)(j0 + r) * Ddim;
            float z = 0.f;
            for (int k = lane; k < Ddim; k += 32)
                z += ir[k] * (sr[k] + kr[k]);
#pragma unroll
            for (int o = 16; o; o >>= 1) z += __shfl_xor_sync(0xffffffffu, z, o);
            if (lane == 0) gate[r] = 1.f / (1.f + expf(-z));
        }
    }

    // -------- barrier-free tf32 split-3 mainloop --------
    float acc[2][8][4];
#pragma unroll
    for (int mi = 0; mi < 2; mi++)
#pragma unroll
        for (int nf = 0; nf < 8; nf++)
#pragma unroll
            for (int c = 0; c < 4; c++) acc[mi][nf][c] = 0.f;

    const float* Abase = state + (size_t)row0 * Ddim;

#pragma unroll 1
    for (int s = 0; s < 64; s++) {
        if (s < 62) cp_wait1(); else cp_wait0();
        __syncwarp();
        int k0 = s * 8;

        // A fragments from global (L1): rows mi*16+gid(+8), cols k0+tig(+4); split hi/lo
        unsigned ah[2][4], al[2][4];
#pragma unroll
        for (int mi = 0; mi < 2; mi++) {
            const float* r0 = Abase + (size_t)(mi * 16 + gid) * Ddim + k0 + tig;
            float f0 = r0[0];
            float f1 = r0[8 * Ddim];
            float f2 = r0[4];
            float f3 = r0[8 * Ddim + 4];
            split_tf32(f0, ah[mi][0], al[mi][0]);
            split_tf32(f1, ah[mi][1], al[mi][1]);
            split_tf32(f2, ah[mi][2], al[mi][2]);
            split_tf32(f3, ah[mi][3], al[mi][3]);
        }

        const uint4* Bs = mybuf + (s & 1) * 256;
#pragma unroll
        for (int half = 0; half < 2; half++) {
            // one LDS.128 per nf: {hi@tig, lo@tig, hi@tig+4, lo@tig+4}
            uint4 bq[4];
#pragma unroll
            for (int q = 0; q < 4; q++) {
                int nf = half * 4 + q;
                bq[q] = Bs[(nf * 8 + gid) * 4 + tig];
            }
            // term hh: 8 independent MMAs
#pragma unroll
            for (int q = 0; q < 4; q++)
#pragma unroll
                for (int mi = 0; mi < 2; mi++) {
                    unsigned bh[2] = {bq[q].x, bq[q].z};
                    mma_tf32(acc[mi][half * 4 + q], ah[mi], bh);
                }
            // term lh
#pragma unroll
            for (int q = 0; q < 4; q++)
#pragma unroll
                for (int mi = 0; mi < 2; mi++) {
                    unsigned bh[2] = {bq[q].x, bq[q].z};
                    mma_tf32(acc[mi][half * 4 + q], al[mi], bh);
                }
            // term hl
#pragma unroll
            for (int q = 0; q < 4; q++)
#pragma unroll
                for (int mi = 0; mi < 2; mi++) {
                    unsigned bl[2] = {bq[q].y, bq[q].w};
                    mma_tf32(acc[mi][half * 4 + q], ah[mi], bl);
                }
        }

        // prefetch slab s+2 into the buffer just consumed (per-warp, no barrier;
        // async writes land >=L2-latency after issue, far after this slab's LDS)
        if (s + 2 < 64) {
            uint4* Ud = mybuf + (s & 1) * 256;
#pragma unroll
            for (int q = 0; q < 8; q++) {
                int idx = lane + 32 * q;
                int col = idx >> 2, p = idx & 3;
                cp_async16(Ud + idx, usrc + (size_t)col * 256 + (s + 2) * 4 + p);
            }
            cp_commit();
        }
    }

    __syncthreads();   // gates visible to all warps

    // -------- epilogue: v = s + g*relu(acc + Q[b] + P[j]); row-norm partials --------
    const float* Qb = g_Q + (size_t)b * Ddim;
    float part[4];
#pragma unroll
    for (int mi = 0; mi < 2; mi++) {
#pragma unroll
        for (int h = 0; h < 2; h++) {
            int r = mi * 16 + h * 8 + gid;          // 0..31
            float g = gate[r];
            const float* Pr = g_P + (size_t)(j0 + r) * Ddim;
            const float* Sr = state + (size_t)(row0 + r) * Ddim;
            float psum = 0.f;
#pragma unroll
            for (int nf = 0; nf < 8; nf++) {
                int c0 = cb + nf * 8 + tig * 2;
                float2 p2 = *reinterpret_cast<const float2*>(Pr + c0);
                float2 q2 = *reinterpret_cast<const float2*>(Qb + c0);
                float2 s2 = *reinterpret_cast<const float2*>(Sr + c0);
                float pre0 = acc[mi][nf][h * 2 + 0] + q2.x + p2.x;
                float pre1 = acc[mi][nf][h * 2 + 1] + q2.y + p2.y;
                float v0 = s2.x + g * fmaxf(pre0, 0.f);
                float v1 = s2.y + g * fmaxf(pre1, 0.f);
                acc[mi][nf][h * 2 + 0] = v0;
                acc[mi][nf][h * 2 + 1] = v1;
                psum += v0 * v0 + v1 * v1;
            }
            part[mi * 2 + h] = psum;
        }
    }
#pragma unroll
    for (int i = 0; i < 4; i++) {
        part[i] += __shfl_xor_sync(0xffffffffu, part[i], 1);
        part[i] += __shfl_xor_sync(0xffffffffu, part[i], 2);
    }
    if (tig == 0) {
#pragma unroll
        for (int mi = 0; mi < 2; mi++)
#pragma unroll
            for (int h = 0; h < 2; h++)
                red[w * 32 + mi * 16 + h * 8 + gid] = part[mi * 2 + h];
    }
    __syncthreads();
    if (tid < 32) {
        float sum = 0.f;
#pragma unroll
        for (int ww = 0; ww < 8; ww++) sum += red[ww * 32 + tid];
        normv[tid] = fmaxf(sqrtf(sum), 1e-12f);
    }
    __syncthreads();

    // out = (v > 0) ? norm : v
#pragma unroll
    for (int mi = 0; mi < 2; mi++) {
#pragma unroll
        for (int h = 0; h < 2; h++) {
            int r = mi * 16 + h * 8 + gid;
            float n = normv[r];
            float* orow = out + (size_t)(row0 + r) * Ddim;
#pragma unroll
            for (int nf = 0; nf < 8; nf++) {
                int c0 = cb + nf * 8 + tig * 2;
                float v0 = acc[mi][nf][h * 2 + 0];
                float v1 = acc[mi][nf][h * 2 + 1];
                float2 o;
                o.x = v0 > 0.f ? n : v0;
                o.y = v1 > 0.f ? n : v1;
                *reinterpret_cast<float2*>(orow + c0) = o;
            }
        }
    }
}

extern "C" void kernel_launch(void* const* d_in, const int* in_sizes, int n_in,
                              void* d_out, int out_size)
{
    const float* inputs = (const float*)d_in[0];
    const float* state  = (const float*)d_in[1];
    const float* keys   = (const float*)d_in[2];
    const float* U      = (const float*)d_in[3];
    const float* V      = (const float*)d_in[4];
    const float* W      = (const float*)d_in[5];
    const float* Ubias  = (const float*)d_in[6];
    float* out = (float*)d_out;
    (void)in_sizes; (void)n_in; (void)out_size;

    // Q (32 blks), P (8 blks), U2T split/transpose (128 blks)
    precompute_kernel<<<168, 256>>>(inputs, keys, V, W, U, Ubias);

    size_t smem = 65536 + (32 + 32 + 8 * 32) * sizeof(float);
    cudaFuncSetAttribute(fused_kernel, cudaFuncAttributeMaxDynamicSharedMemorySize, (int)smem);
    fused_kernel<<<(Bdim * Jdim) / 32, 256, smem>>>(inputs, state, keys, out);
}